// round 10
// baseline (speedup 1.0000x reference)
#include <cuda_runtime.h>

// ---------------- problem constants (fixed shapes) ----------------
constexpr int   NN   = 100000;   // nodes
constexpr int   NE   = 1600000;  // edges
constexpr int   FIN  = 128;
constexpr int   HID  = 64;
constexpr int   TOUT = 10;
constexpr int   MAXB = 512;      // partial-max blocks
constexpr int   NB   = (NN + 255) / 256;   // 391 node blocks
constexpr int   NG2  = NN / 2;             // 50000 row pairs
#define ALPHA 0.1f

// ---------------- device scratch (no allocations allowed) ----------------
__device__ int   g_is64;           // 1 if edge_index buffer is int64
__device__ float g_part[MAXB];     // per-block time maxima
__device__ float g_tmax;           // final max
__device__ int2  g_edge[NE];       // (row, col) as int32
__device__ float g_w[NE];          // decay -> ew (in place)
__device__ float g_deg[NN];
__device__ float g_dinv[NN];
__device__ float g_dinv2[NN];      // deg2 accumulator, then dinv2
__device__ float g_nself[NN];      // self-loop norm = dinv2^2
__device__ int   g_cnt[NN];        // in-degree counts (by col)
__device__ int   g_bsum[NB];       // scan: per-block sums
__device__ int   g_boff[NB];       // scan: per-block exclusive offsets
__device__ int   g_ptr[NN + 1];    // CSR row pointers (by col)
__device__ int   g_pos[NN];        // fill cursors
__device__ int2  g_csre[NE];       // CSR edge records {src, norm bits}
__device__ float g_HA[NN * HID];   // H0, later overwritten by H1b
__device__ float g_AG[NN * HID];   // aggregation output (written once/node)

// ---------------- kernels ----------------

__global__ void k_detect(const int* __restrict__ ei32) {
    int odd_or = 0;
    #pragma unroll
    for (int k = 1; k < 64; k += 2) odd_or |= ei32[k];
    g_is64 = (odd_or == 0) ? 1 : 0;
}

__global__ void k_zero() {
    int i = blockIdx.x * blockDim.x + threadIdx.x;
    if (i < NN) { g_deg[i] = 0.f; g_dinv2[i] = 0.f; g_cnt[i] = 0; }
}

__global__ void k_max1(const float* __restrict__ t) {
    __shared__ float sm[8];
    float m = 0.f;  // times uniform[0,1): >= 0
    for (int i = blockIdx.x * blockDim.x + threadIdx.x; i < NE; i += gridDim.x * blockDim.x)
        m = fmaxf(m, t[i]);
    #pragma unroll
    for (int o = 16; o; o >>= 1) m = fmaxf(m, __shfl_xor_sync(0xffffffffu, m, o));
    if ((threadIdx.x & 31) == 0) sm[threadIdx.x >> 5] = m;
    __syncthreads();
    if (threadIdx.x < 8) {
        m = sm[threadIdx.x];
        #pragma unroll
        for (int o = 4; o; o >>= 1) m = fmaxf(m, __shfl_xor_sync(0xffu, m, o));
        if (threadIdx.x == 0) g_part[blockIdx.x] = m;
    }
}

__global__ void k_max2() {
    __shared__ float sm[16];
    float m = g_part[threadIdx.x];
    #pragma unroll
    for (int o = 16; o; o >>= 1) m = fmaxf(m, __shfl_xor_sync(0xffffffffu, m, o));
    if ((threadIdx.x & 31) == 0) sm[threadIdx.x >> 5] = m;
    __syncthreads();
    if (threadIdx.x < 16) {
        m = sm[threadIdx.x];
        #pragma unroll
        for (int o = 8; o; o >>= 1) m = fmaxf(m, __shfl_xor_sync(0xffffu, m, o));
        if (threadIdx.x == 0) g_tmax = m;
    }
}

__global__ void k_decay_deg(const int* __restrict__ ei, const float* __restrict__ t) {
    int e = blockIdx.x * blockDim.x + threadIdx.x;
    if (e >= NE) return;
    int r, c;
    if (g_is64) {
        const long long* e64 = (const long long*)ei;
        r = (int)e64[e];
        c = (int)e64[NE + e];
    } else {
        r = ei[e];
        c = ei[NE + e];
    }
    g_edge[e] = make_int2(r, c);
    float d = expf(ALPHA * (t[e] - g_tmax));
    g_w[e] = d;
    atomicAdd(&g_deg[r], d);
    atomicAdd(&g_cnt[c], 1);
}

__global__ void k_dinv() {
    int i = blockIdx.x * blockDim.x + threadIdx.x;
    if (i >= NN) return;
    float d = g_deg[i];
    g_dinv[i] = (d > 0.f) ? rsqrtf(d) : 0.f;
}

__global__ void k_ew_deg2() {
    int e = blockIdx.x * blockDim.x + threadIdx.x;
    if (e >= NE) return;
    int2 rc = g_edge[e];
    float ew = g_dinv[rc.x] * g_w[e] * g_dinv[rc.y];
    g_w[e] = ew;
    atomicAdd(&g_dinv2[rc.y], ew);
}

__global__ void k_dinv2() {
    int i = blockIdx.x * blockDim.x + threadIdx.x;
    if (i >= NN) return;
    float d2 = g_dinv2[i] + 1.0f;
    float di = rsqrtf(d2);
    g_dinv2[i] = di;
    g_nself[i] = di * di;
}

// ---- parallel 3-phase exclusive scan of g_cnt ----
__global__ void k_scanA() {
    __shared__ int sm[8];
    int i = blockIdx.x * blockDim.x + threadIdx.x;
    int v = (i < NN) ? g_cnt[i] : 0;
    #pragma unroll
    for (int o = 16; o; o >>= 1) v += __shfl_xor_sync(0xffffffffu, v, o);
    if ((threadIdx.x & 31) == 0) sm[threadIdx.x >> 5] = v;
    __syncthreads();
    if (threadIdx.x < 8) {
        v = sm[threadIdx.x];
        #pragma unroll
        for (int o = 4; o; o >>= 1) v += __shfl_xor_sync(0xffu, v, o);
        if (threadIdx.x == 0) g_bsum[blockIdx.x] = v;
    }
}

__global__ void k_scanB() {
    __shared__ int ws[16];
    int t = threadIdx.x, lane = t & 31, wid = t >> 5;
    int v = (t < NB) ? g_bsum[t] : 0;
    int inc = v;
    #pragma unroll
    for (int o = 1; o < 32; o <<= 1) {
        int u = __shfl_up_sync(0xffffffffu, inc, o);
        if (lane >= o) inc += u;
    }
    if (lane == 31) ws[wid] = inc;
    __syncthreads();
    if (wid == 0 && lane < 16) {
        int w = ws[lane];
        #pragma unroll
        for (int o = 1; o < 16; o <<= 1) {
            int u = __shfl_up_sync(0xffffu, w, o);
            if (lane >= o) w += u;
        }
        ws[lane] = w;
    }
    __syncthreads();
    int excl = inc - v + (wid ? ws[wid - 1] : 0);
    if (t < NB) g_boff[t] = excl;
}

__global__ void k_scanC() {
    __shared__ int ws[8];
    int i = blockIdx.x * blockDim.x + threadIdx.x;
    int lane = threadIdx.x & 31, wid = threadIdx.x >> 5;
    int c = (i < NN) ? g_cnt[i] : 0;
    int inc = c;
    #pragma unroll
    for (int o = 1; o < 32; o <<= 1) {
        int u = __shfl_up_sync(0xffffffffu, inc, o);
        if (lane >= o) inc += u;
    }
    if (lane == 31) ws[wid] = inc;
    __syncthreads();
    if (wid == 0 && lane < 8) {
        int w = ws[lane];
        #pragma unroll
        for (int o = 1; o < 8; o <<= 1) {
            int u = __shfl_up_sync(0xffu, w, o);
            if (lane >= o) w += u;
        }
        ws[lane] = w;
    }
    __syncthreads();
    int ex = inc - c + (wid ? ws[wid - 1] : 0) + g_boff[blockIdx.x];
    if (i < NN) { g_ptr[i] = ex; g_pos[i] = ex; }
    if (i == NN - 1) g_ptr[NN] = ex + c;
}

__global__ void k_fill() {
    int e = blockIdx.x * blockDim.x + threadIdx.x;
    if (e >= NE) return;
    int2 rc = g_edge[e];
    float nm = g_dinv2[rc.x] * g_w[e] * g_dinv2[rc.y];
    int p = atomicAdd(&g_pos[rc.y], 1);
    g_csre[p] = make_int2(rc.x, __float_as_int(nm));
}

// HA = x @ W1: thread computes 2 rows x 16 cols; 3 blocks/SM for occupancy
__global__ void __launch_bounds__(256, 3)
k_gemm1(const float* __restrict__ x, const float* __restrict__ W1) {
    __shared__ float Ws[FIN * HID]; // 32 KB
    {
        const float4* w4 = (const float4*)W1;
        float4* s4 = (float4*)Ws;
        for (int i = threadIdx.x; i < FIN * HID / 4; i += blockDim.x) s4[i] = w4[i];
    }
    __syncthreads();
    int gt    = blockIdx.x * blockDim.x + threadIdx.x;
    int grp   = gt >> 2;          // row pair
    int slice = gt & 3;           // 16-col slice
    if (grp >= NG2) return;
    int r0 = grp * 2;
    const float4* xr0 = (const float4*)(x + (long)(r0 + 0) * FIN);
    const float4* xr1 = (const float4*)(x + (long)(r0 + 1) * FIN);
    float acc[2][16];
    #pragma unroll
    for (int i = 0; i < 2; i++)
        #pragma unroll
        for (int j = 0; j < 16; j++) acc[i][j] = 0.f;
    const int cb = slice * 16;
    #pragma unroll 4
    for (int k4 = 0; k4 < FIN / 4; k4++) {
        float4 xv0 = xr0[k4];
        float4 xv1 = xr1[k4];
        #pragma unroll
        for (int kk = 0; kk < 4; kk++) {
            const float4* wr = (const float4*)&Ws[(k4 * 4 + kk) * HID + cb];
            float4 w0 = wr[0], w1 = wr[1], w2 = wr[2], w3 = wr[3];
            float xs0 = (kk == 0) ? xv0.x : (kk == 1) ? xv0.y : (kk == 2) ? xv0.z : xv0.w;
            float xs1 = (kk == 0) ? xv1.x : (kk == 1) ? xv1.y : (kk == 2) ? xv1.z : xv1.w;
            acc[0][0]  += xs0 * w0.x; acc[0][1]  += xs0 * w0.y;
            acc[0][2]  += xs0 * w0.z; acc[0][3]  += xs0 * w0.w;
            acc[0][4]  += xs0 * w1.x; acc[0][5]  += xs0 * w1.y;
            acc[0][6]  += xs0 * w1.z; acc[0][7]  += xs0 * w1.w;
            acc[0][8]  += xs0 * w2.x; acc[0][9]  += xs0 * w2.y;
            acc[0][10] += xs0 * w2.z; acc[0][11] += xs0 * w2.w;
            acc[0][12] += xs0 * w3.x; acc[0][13] += xs0 * w3.y;
            acc[0][14] += xs0 * w3.z; acc[0][15] += xs0 * w3.w;
            acc[1][0]  += xs1 * w0.x; acc[1][1]  += xs1 * w0.y;
            acc[1][2]  += xs1 * w0.z; acc[1][3]  += xs1 * w0.w;
            acc[1][4]  += xs1 * w1.x; acc[1][5]  += xs1 * w1.y;
            acc[1][6]  += xs1 * w1.z; acc[1][7]  += xs1 * w1.w;
            acc[1][8]  += xs1 * w2.x; acc[1][9]  += xs1 * w2.y;
            acc[1][10] += xs1 * w2.z; acc[1][11] += xs1 * w2.w;
            acc[1][12] += xs1 * w3.x; acc[1][13] += xs1 * w3.y;
            acc[1][14] += xs1 * w3.z; acc[1][15] += xs1 * w3.w;
        }
    }
    #pragma unroll
    for (int i = 0; i < 2; i++) {
        float4* dst = (float4*)(g_HA + (long)(r0 + i) * HID + cb);
        #pragma unroll
        for (int j = 0; j < 4; j++)
            dst[j] = make_float4(acc[i][4*j], acc[i][4*j+1], acc[i][4*j+2], acc[i][4*j+3]);
    }
}

// gather-SpMM: warp per destination node, self-loop folded in, x4 unrolled
__global__ void k_spmm_csr() {
    int i = (blockIdx.x * blockDim.x + threadIdx.x) >> 5;
    if (i >= NN) return;
    int lane = threadIdx.x & 31;
    int beg = g_ptr[i], end = g_ptr[i + 1];
    float  ns = g_nself[i];
    float2 h  = ((const float2*)(g_HA + (long)i * HID))[lane];
    float a0 = ns * h.x, a1 = ns * h.y;
    int e = beg;
    for (; e + 4 <= end; e += 4) {
        int2 r0 = g_csre[e + 0];
        int2 r1 = g_csre[e + 1];
        int2 r2 = g_csre[e + 2];
        int2 r3 = g_csre[e + 3];
        float2 v0 = ((const float2*)(g_HA + (long)r0.x * HID))[lane];
        float2 v1 = ((const float2*)(g_HA + (long)r1.x * HID))[lane];
        float2 v2 = ((const float2*)(g_HA + (long)r2.x * HID))[lane];
        float2 v3 = ((const float2*)(g_HA + (long)r3.x * HID))[lane];
        float n0 = __int_as_float(r0.y), n1 = __int_as_float(r1.y);
        float n2 = __int_as_float(r2.y), n3 = __int_as_float(r3.y);
        a0 += n0 * v0.x; a1 += n0 * v0.y;
        a0 += n1 * v1.x; a1 += n1 * v1.y;
        a0 += n2 * v2.x; a1 += n2 * v2.y;
        a0 += n3 * v3.x; a1 += n3 * v3.y;
    }
    for (; e < end; e++) {
        int2  rec = g_csre[e];
        float nm  = __int_as_float(rec.y);
        float2 v  = ((const float2*)(g_HA + (long)rec.x * HID))[lane];
        a0 += nm * v.x;
        a1 += nm * v.y;
    }
    ((float2*)(g_AG + (long)i * HID))[lane] = make_float2(a0, a1);
}

// h1 = relu(AG + b1); HA <- h1 @ W2 : 2 rows x 16 cols per thread
__global__ void __launch_bounds__(256, 3)
k_layer1(const float* __restrict__ b1, const float* __restrict__ W2) {
    __shared__ float Ws[HID * HID]; // 16 KB
    __shared__ float bs[HID];
    {
        const float4* w4 = (const float4*)W2;
        float4* s4 = (float4*)Ws;
        for (int i = threadIdx.x; i < HID * HID / 4; i += blockDim.x) s4[i] = w4[i];
        if (threadIdx.x < HID) bs[threadIdx.x] = b1[threadIdx.x];
    }
    __syncthreads();
    int gt    = blockIdx.x * blockDim.x + threadIdx.x;
    int grp   = gt >> 2;
    int slice = gt & 3;
    if (grp >= NG2) return;
    int r0 = grp * 2;
    const float4* a0p = (const float4*)(g_AG + (long)(r0 + 0) * HID);
    const float4* a1p = (const float4*)(g_AG + (long)(r0 + 1) * HID);
    const float4* b4  = (const float4*)bs;
    float acc[2][16];
    #pragma unroll
    for (int i = 0; i < 2; i++)
        #pragma unroll
        for (int j = 0; j < 16; j++) acc[i][j] = 0.f;
    const int cb = slice * 16;
    #pragma unroll 4
    for (int k4 = 0; k4 < HID / 4; k4++) {
        float4 bv = b4[k4];
        float4 av0 = a0p[k4];
        float4 av1 = a1p[k4];
        float hs0[4] = { fmaxf(av0.x + bv.x, 0.f), fmaxf(av0.y + bv.y, 0.f),
                         fmaxf(av0.z + bv.z, 0.f), fmaxf(av0.w + bv.w, 0.f) };
        float hs1[4] = { fmaxf(av1.x + bv.x, 0.f), fmaxf(av1.y + bv.y, 0.f),
                         fmaxf(av1.z + bv.z, 0.f), fmaxf(av1.w + bv.w, 0.f) };
        #pragma unroll
        for (int kk = 0; kk < 4; kk++) {
            const float4* wr = (const float4*)&Ws[(k4 * 4 + kk) * HID + cb];
            float4 w0 = wr[0], w1 = wr[1], w2 = wr[2], w3 = wr[3];
            float xs0 = hs0[kk], xs1 = hs1[kk];
            acc[0][0]  += xs0 * w0.x; acc[0][1]  += xs0 * w0.y;
            acc[0][2]  += xs0 * w0.z; acc[0][3]  += xs0 * w0.w;
            acc[0][4]  += xs0 * w1.x; acc[0][5]  += xs0 * w1.y;
            acc[0][6]  += xs0 * w1.z; acc[0][7]  += xs0 * w1.w;
            acc[0][8]  += xs0 * w2.x; acc[0][9]  += xs0 * w2.y;
            acc[0][10] += xs0 * w2.z; acc[0][11] += xs0 * w2.w;
            acc[0][12] += xs0 * w3.x; acc[0][13] += xs0 * w3.y;
            acc[0][14] += xs0 * w3.z; acc[0][15] += xs0 * w3.w;
            acc[1][0]  += xs1 * w0.x; acc[1][1]  += xs1 * w0.y;
            acc[1][2]  += xs1 * w0.z; acc[1][3]  += xs1 * w0.w;
            acc[1][4]  += xs1 * w1.x; acc[1][5]  += xs1 * w1.y;
            acc[1][6]  += xs1 * w1.z; acc[1][7]  += xs1 * w1.w;
            acc[1][8]  += xs1 * w2.x; acc[1][9]  += xs1 * w2.y;
            acc[1][10] += xs1 * w2.z; acc[1][11] += xs1 * w2.w;
            acc[1][12] += xs1 * w3.x; acc[1][13] += xs1 * w3.y;
            acc[1][14] += xs1 * w3.z; acc[1][15] += xs1 * w3.w;
        }
    }
    #pragma unroll
    for (int i = 0; i < 2; i++) {
        float4* dst = (float4*)(g_HA + (long)(r0 + i) * HID + cb);
        #pragma unroll
        for (int j = 0; j < 4; j++)
            dst[j] = make_float4(acc[i][4*j], acc[i][4*j+1], acc[i][4*j+2], acc[i][4*j+3]);
    }
}

// h2 = relu(AG + b2); out = h2 @ Wout + bout : thread per row
__global__ void k_out(const float* __restrict__ b2, const float* __restrict__ Wout,
                      const float* __restrict__ bout, float* __restrict__ out) {
    __shared__ float Ws[HID * TOUT];
    __shared__ float bs[HID];
    __shared__ float bo[TOUT];
    for (int i = threadIdx.x; i < HID * TOUT; i += blockDim.x) Ws[i] = Wout[i];
    if (threadIdx.x < HID)  bs[threadIdx.x] = b2[threadIdx.x];
    if (threadIdx.x < TOUT) bo[threadIdx.x] = bout[threadIdx.x];
    __syncthreads();
    int row = blockIdx.x * blockDim.x + threadIdx.x;
    if (row >= NN) return;
    const float4* ar = (const float4*)(g_AG + (long)row * HID);
    const float4* b4 = (const float4*)bs;
    float acc[TOUT];
    #pragma unroll
    for (int j = 0; j < TOUT; j++) acc[j] = bo[j];
    #pragma unroll 2
    for (int k4 = 0; k4 < HID / 4; k4++) {
        float4 av = ar[k4];
        float4 bv = b4[k4];
        float hs[4] = { fmaxf(av.x + bv.x, 0.f), fmaxf(av.y + bv.y, 0.f),
                        fmaxf(av.z + bv.z, 0.f), fmaxf(av.w + bv.w, 0.f) };
        #pragma unroll
        for (int kk = 0; kk < 4; kk++) {
            float xs = hs[kk];
            const float* wr = &Ws[(k4 * 4 + kk) * TOUT];
            #pragma unroll
            for (int j = 0; j < TOUT; j++) acc[j] += xs * wr[j];
        }
    }
    float* o = out + (long)row * TOUT;
    #pragma unroll
    for (int j = 0; j < TOUT; j++) o[j] = acc[j];
}

// ---------------- launch ----------------
extern "C" void kernel_launch(void* const* d_in, const int* in_sizes, int n_in,
                              void* d_out, int out_size) {
    const float* x    = (const float*)d_in[0];
    const int*   ei   = (const int*)d_in[1];
    const float* et   = (const float*)d_in[2];
    const float* W1   = (const float*)d_in[3];
    const float* b1   = (const float*)d_in[4];
    const float* W2   = (const float*)d_in[5];
    const float* b2   = (const float*)d_in[6];
    const float* Wout = (const float*)d_in[7];
    const float* bout = (const float*)d_in[8];
    float*       out  = (float*)d_out;

    const int TB = 256;
    const int GEMMB = (NG2 * 4 + TB - 1) / TB;   // 4 slices per row pair
    k_detect<<<1, 1>>>(ei);
    k_zero<<<NB, TB>>>();
    k_max1<<<MAXB, TB>>>(et);
    k_gemm1<<<GEMMB, TB>>>(x, W1);       // slot 4: profiled by ncu sampler
    k_max2<<<1, MAXB>>>();
    k_decay_deg<<<(NE + TB - 1) / TB, TB>>>(ei, et);
    k_dinv <<<NB, TB>>>();
    k_ew_deg2<<<(NE + TB - 1) / TB, TB>>>();
    k_dinv2<<<NB, TB>>>();
    k_scanA<<<NB, TB>>>();
    k_scanB<<<1, 512>>>();
    k_scanC<<<NB, TB>>>();
    k_fill <<<(NE + TB - 1) / TB, TB>>>();

    k_spmm_csr<<<(NN * 32 + TB - 1) / TB, TB>>>();
    k_layer1<<<GEMMB, TB>>>(b1, W2);
    k_spmm_csr<<<(NN * 32 + TB - 1) / TB, TB>>>();
    k_out<<<NB, TB>>>(b2, Wout, bout, out);
}

// round 11
// speedup vs baseline: 1.2375x; 1.2375x over previous
#include <cuda_runtime.h>

// ---------------- problem constants (fixed shapes) ----------------
constexpr int   NN   = 100000;   // nodes
constexpr int   NE   = 1600000;  // edges
constexpr int   FIN  = 128;
constexpr int   HID  = 64;
constexpr int   TOUT = 10;
constexpr int   MAXB = 512;      // partial-max blocks
constexpr int   NB   = (NN + 255) / 256;   // 391 node blocks
constexpr int   NG   = NN / 4;             // 25000 row groups of 4
#define ALPHA 0.1f

// ---------------- f32x2 packed math helpers ----------------
__device__ __forceinline__ unsigned long long pack2(float x, float y) {
    unsigned long long r;
    asm("mov.b64 %0, {%1, %2};" : "=l"(r) : "f"(x), "f"(y));
    return r;
}
__device__ __forceinline__ void ffma2(unsigned long long& d,
                                      unsigned long long a, unsigned long long b) {
    asm("fma.rn.f32x2 %0, %1, %2, %0;" : "+l"(d) : "l"(a), "l"(b));
}

// ---------------- device scratch (no allocations allowed) ----------------
__device__ int   g_is64;           // 1 if edge_index buffer is int64
__device__ float g_part[MAXB];     // per-block time maxima
__device__ float g_tmax;           // final max
__device__ int2  g_edge[NE];       // (row, col) as int32
__device__ float g_w[NE];          // decay -> ew (in place)
__device__ float g_deg[NN];
__device__ float g_dinv[NN];
__device__ float g_dinv2[NN];      // deg2 accumulator, then dinv2
__device__ float g_nself[NN];      // self-loop norm = dinv2^2
__device__ int   g_cnt[NN];        // in-degree counts (by col)
__device__ int   g_bsum[NB];       // scan: per-block sums
__device__ int   g_boff[NB];       // scan: per-block exclusive offsets
__device__ int   g_ptr[NN + 1];    // CSR row pointers (by col)
__device__ int   g_pos[NN];        // fill cursors
__device__ int2  g_csre[NE];       // CSR edge records {src, norm bits}
__device__ float g_HA[NN * HID];   // H0, later overwritten by H1b
__device__ float g_AG[NN * HID];   // aggregation output (written once/node)

// ---------------- kernels ----------------

// detect dtype + zero per-node accumulators (fused)
__global__ void k_detect_zero(const int* __restrict__ ei32) {
    int i = blockIdx.x * blockDim.x + threadIdx.x;
    if (i == 0) {
        int odd_or = 0;
        #pragma unroll
        for (int k = 1; k < 64; k += 2) odd_or |= ei32[k];
        g_is64 = (odd_or == 0) ? 1 : 0;
    }
    if (i < NN) { g_deg[i] = 0.f; g_dinv2[i] = 0.f; g_cnt[i] = 0; }
}

__global__ void k_max1(const float* __restrict__ t) {
    __shared__ float sm[8];
    float m = 0.f;  // times uniform[0,1): >= 0
    for (int i = blockIdx.x * blockDim.x + threadIdx.x; i < NE; i += gridDim.x * blockDim.x)
        m = fmaxf(m, t[i]);
    #pragma unroll
    for (int o = 16; o; o >>= 1) m = fmaxf(m, __shfl_xor_sync(0xffffffffu, m, o));
    if ((threadIdx.x & 31) == 0) sm[threadIdx.x >> 5] = m;
    __syncthreads();
    if (threadIdx.x < 8) {
        m = sm[threadIdx.x];
        #pragma unroll
        for (int o = 4; o; o >>= 1) m = fmaxf(m, __shfl_xor_sync(0xffu, m, o));
        if (threadIdx.x == 0) g_part[blockIdx.x] = m;
    }
}

__global__ void k_max2() {
    __shared__ float sm[16];
    float m = g_part[threadIdx.x];
    #pragma unroll
    for (int o = 16; o; o >>= 1) m = fmaxf(m, __shfl_xor_sync(0xffffffffu, m, o));
    if ((threadIdx.x & 31) == 0) sm[threadIdx.x >> 5] = m;
    __syncthreads();
    if (threadIdx.x < 16) {
        m = sm[threadIdx.x];
        #pragma unroll
        for (int o = 8; o; o >>= 1) m = fmaxf(m, __shfl_xor_sync(0xffffu, m, o));
        if (threadIdx.x == 0) g_tmax = m;
    }
}

__global__ void k_decay_deg(const int* __restrict__ ei, const float* __restrict__ t) {
    int e = blockIdx.x * blockDim.x + threadIdx.x;
    if (e >= NE) return;
    int r, c;
    if (g_is64) {
        const long long* e64 = (const long long*)ei;
        r = (int)e64[e];
        c = (int)e64[NE + e];
    } else {
        r = ei[e];
        c = ei[NE + e];
    }
    g_edge[e] = make_int2(r, c);
    float d = expf(ALPHA * (t[e] - g_tmax));
    g_w[e] = d;
    atomicAdd(&g_deg[r], d);
    atomicAdd(&g_cnt[c], 1);
}

__global__ void k_dinv() {
    int i = blockIdx.x * blockDim.x + threadIdx.x;
    if (i >= NN) return;
    float d = g_deg[i];
    g_dinv[i] = (d > 0.f) ? rsqrtf(d) : 0.f;
}

__global__ void k_ew_deg2() {
    int e = blockIdx.x * blockDim.x + threadIdx.x;
    if (e >= NE) return;
    int2 rc = g_edge[e];
    float ew = g_dinv[rc.x] * g_w[e] * g_dinv[rc.y];
    g_w[e] = ew;
    atomicAdd(&g_dinv2[rc.y], ew);
}

// ---- parallel 3-phase exclusive scan of g_cnt ----
__global__ void k_scanA() {
    __shared__ int sm[8];
    int i = blockIdx.x * blockDim.x + threadIdx.x;
    int v = (i < NN) ? g_cnt[i] : 0;
    #pragma unroll
    for (int o = 16; o; o >>= 1) v += __shfl_xor_sync(0xffffffffu, v, o);
    if ((threadIdx.x & 31) == 0) sm[threadIdx.x >> 5] = v;
    __syncthreads();
    if (threadIdx.x < 8) {
        v = sm[threadIdx.x];
        #pragma unroll
        for (int o = 4; o; o >>= 1) v += __shfl_xor_sync(0xffu, v, o);
        if (threadIdx.x == 0) g_bsum[blockIdx.x] = v;
    }
}

__global__ void k_scanB() {
    __shared__ int ws[16];
    int t = threadIdx.x, lane = t & 31, wid = t >> 5;
    int v = (t < NB) ? g_bsum[t] : 0;
    int inc = v;
    #pragma unroll
    for (int o = 1; o < 32; o <<= 1) {
        int u = __shfl_up_sync(0xffffffffu, inc, o);
        if (lane >= o) inc += u;
    }
    if (lane == 31) ws[wid] = inc;
    __syncthreads();
    if (wid == 0 && lane < 16) {
        int w = ws[lane];
        #pragma unroll
        for (int o = 1; o < 16; o <<= 1) {
            int u = __shfl_up_sync(0xffffu, w, o);
            if (lane >= o) w += u;
        }
        ws[lane] = w;
    }
    __syncthreads();
    int excl = inc - v + (wid ? ws[wid - 1] : 0);
    if (t < NB) g_boff[t] = excl;
}

// scanC also finalizes dinv2/nself (fused; runs after ew_deg2)
__global__ void k_scanC() {
    __shared__ int ws[8];
    int i = blockIdx.x * blockDim.x + threadIdx.x;
    int lane = threadIdx.x & 31, wid = threadIdx.x >> 5;
    int c = (i < NN) ? g_cnt[i] : 0;
    int inc = c;
    #pragma unroll
    for (int o = 1; o < 32; o <<= 1) {
        int u = __shfl_up_sync(0xffffffffu, inc, o);
        if (lane >= o) inc += u;
    }
    if (lane == 31) ws[wid] = inc;
    __syncthreads();
    if (wid == 0 && lane < 8) {
        int w = ws[lane];
        #pragma unroll
        for (int o = 1; o < 8; o <<= 1) {
            int u = __shfl_up_sync(0xffu, w, o);
            if (lane >= o) w += u;
        }
        ws[lane] = w;
    }
    __syncthreads();
    int ex = inc - c + (wid ? ws[wid - 1] : 0) + g_boff[blockIdx.x];
    if (i < NN) {
        g_ptr[i] = ex;
        g_pos[i] = ex;
        float d2 = g_dinv2[i] + 1.0f;     // + self loop weight 1
        float di = rsqrtf(d2);
        g_dinv2[i] = di;
        g_nself[i] = di * di;
    }
    if (i == NN - 1) g_ptr[NN] = ex + c;
}

__global__ void k_fill() {
    int e = blockIdx.x * blockDim.x + threadIdx.x;
    if (e >= NE) return;
    int2 rc = g_edge[e];
    float nm = g_dinv2[rc.x] * g_w[e] * g_dinv2[rc.y];
    int p = atomicAdd(&g_pos[rc.y], 1);
    g_csre[p] = make_int2(rc.x, __float_as_int(nm));
}

// HA = x @ W1: thread computes 4 rows x 16 cols, f32x2 packed FMA
__global__ void __launch_bounds__(256, 2)
k_gemm1(const float* __restrict__ x, const float* __restrict__ W1) {
    __shared__ float Ws[FIN * HID]; // 32 KB
    {
        const float4* w4 = (const float4*)W1;
        float4* s4 = (float4*)Ws;
        for (int i = threadIdx.x; i < FIN * HID / 4; i += blockDim.x) s4[i] = w4[i];
    }
    __syncthreads();
    int gt    = blockIdx.x * blockDim.x + threadIdx.x;
    int grp   = gt >> 2;          // row group (4 rows)
    int slice = gt & 3;           // 16-col slice
    if (grp >= NG) return;
    int r0 = grp * 4;
    const float4* xr0 = (const float4*)(x + (long)(r0 + 0) * FIN);
    const float4* xr1 = (const float4*)(x + (long)(r0 + 1) * FIN);
    const float4* xr2 = (const float4*)(x + (long)(r0 + 2) * FIN);
    const float4* xr3 = (const float4*)(x + (long)(r0 + 3) * FIN);
    unsigned long long acc[4][8];   // 4 rows x 8 f32x2 pairs (16 cols)
    #pragma unroll
    for (int i = 0; i < 4; i++)
        #pragma unroll
        for (int j = 0; j < 8; j++) acc[i][j] = 0ull;
    const int cb = slice * 16;
    #pragma unroll 2
    for (int k4 = 0; k4 < FIN / 4; k4++) {
        float4 xv[4] = { xr0[k4], xr1[k4], xr2[k4], xr3[k4] };
        #pragma unroll
        for (int kk = 0; kk < 4; kk++) {
            const ulonglong2* wr = (const ulonglong2*)&Ws[(k4 * 4 + kk) * HID + cb];
            ulonglong2 p0 = wr[0], p1 = wr[1], p2 = wr[2], p3 = wr[3];
            unsigned long long w[8] = { p0.x, p0.y, p1.x, p1.y, p2.x, p2.y, p3.x, p3.y };
            #pragma unroll
            for (int i = 0; i < 4; i++) {
                float xs = (kk == 0) ? xv[i].x : (kk == 1) ? xv[i].y
                         : (kk == 2) ? xv[i].z : xv[i].w;
                unsigned long long xs2 = pack2(xs, xs);
                #pragma unroll
                for (int j = 0; j < 8; j++) ffma2(acc[i][j], xs2, w[j]);
            }
        }
    }
    #pragma unroll
    for (int i = 0; i < 4; i++) {
        ulonglong2* dst = (ulonglong2*)(g_HA + (long)(r0 + i) * HID + cb);
        #pragma unroll
        for (int j = 0; j < 4; j++)
            dst[j] = make_ulonglong2(acc[i][2 * j], acc[i][2 * j + 1]);
    }
}

// gather-SpMM: warp per destination node, self-loop folded in, x4 unrolled
__global__ void k_spmm_csr() {
    int i = (blockIdx.x * blockDim.x + threadIdx.x) >> 5;
    if (i >= NN) return;
    int lane = threadIdx.x & 31;
    int beg = g_ptr[i], end = g_ptr[i + 1];
    float  ns = g_nself[i];
    float2 h  = ((const float2*)(g_HA + (long)i * HID))[lane];
    float a0 = ns * h.x, a1 = ns * h.y;
    int e = beg;
    for (; e + 4 <= end; e += 4) {
        int2 r0 = g_csre[e + 0];
        int2 r1 = g_csre[e + 1];
        int2 r2 = g_csre[e + 2];
        int2 r3 = g_csre[e + 3];
        float2 v0 = ((const float2*)(g_HA + (long)r0.x * HID))[lane];
        float2 v1 = ((const float2*)(g_HA + (long)r1.x * HID))[lane];
        float2 v2 = ((const float2*)(g_HA + (long)r2.x * HID))[lane];
        float2 v3 = ((const float2*)(g_HA + (long)r3.x * HID))[lane];
        float n0 = __int_as_float(r0.y), n1 = __int_as_float(r1.y);
        float n2 = __int_as_float(r2.y), n3 = __int_as_float(r3.y);
        a0 += n0 * v0.x; a1 += n0 * v0.y;
        a0 += n1 * v1.x; a1 += n1 * v1.y;
        a0 += n2 * v2.x; a1 += n2 * v2.y;
        a0 += n3 * v3.x; a1 += n3 * v3.y;
    }
    for (; e < end; e++) {
        int2  rec = g_csre[e];
        float nm  = __int_as_float(rec.y);
        float2 v  = ((const float2*)(g_HA + (long)rec.x * HID))[lane];
        a0 += nm * v.x;
        a1 += nm * v.y;
    }
    ((float2*)(g_AG + (long)i * HID))[lane] = make_float2(a0, a1);
}

// h1 = relu(AG + b1); HA <- h1 @ W2 : 4 rows x 16 cols, f32x2 packed FMA
__global__ void __launch_bounds__(256, 2)
k_layer1(const float* __restrict__ b1, const float* __restrict__ W2) {
    __shared__ float Ws[HID * HID]; // 16 KB
    __shared__ float bs[HID];
    {
        const float4* w4 = (const float4*)W2;
        float4* s4 = (float4*)Ws;
        for (int i = threadIdx.x; i < HID * HID / 4; i += blockDim.x) s4[i] = w4[i];
        if (threadIdx.x < HID) bs[threadIdx.x] = b1[threadIdx.x];
    }
    __syncthreads();
    int gt    = blockIdx.x * blockDim.x + threadIdx.x;
    int grp   = gt >> 2;
    int slice = gt & 3;
    if (grp >= NG) return;
    int r0 = grp * 4;
    const float4* a0p = (const float4*)(g_AG + (long)(r0 + 0) * HID);
    const float4* a1p = (const float4*)(g_AG + (long)(r0 + 1) * HID);
    const float4* a2p = (const float4*)(g_AG + (long)(r0 + 2) * HID);
    const float4* a3p = (const float4*)(g_AG + (long)(r0 + 3) * HID);
    const float4* b4  = (const float4*)bs;
    unsigned long long acc[4][8];
    #pragma unroll
    for (int i = 0; i < 4; i++)
        #pragma unroll
        for (int j = 0; j < 8; j++) acc[i][j] = 0ull;
    const int cb = slice * 16;
    #pragma unroll 2
    for (int k4 = 0; k4 < HID / 4; k4++) {
        float4 bv = b4[k4];
        float4 av[4] = { a0p[k4], a1p[k4], a2p[k4], a3p[k4] };
        float hs[4][4];
        #pragma unroll
        for (int i = 0; i < 4; i++) {
            hs[i][0] = fmaxf(av[i].x + bv.x, 0.f);
            hs[i][1] = fmaxf(av[i].y + bv.y, 0.f);
            hs[i][2] = fmaxf(av[i].z + bv.z, 0.f);
            hs[i][3] = fmaxf(av[i].w + bv.w, 0.f);
        }
        #pragma unroll
        for (int kk = 0; kk < 4; kk++) {
            const ulonglong2* wr = (const ulonglong2*)&Ws[(k4 * 4 + kk) * HID + cb];
            ulonglong2 p0 = wr[0], p1 = wr[1], p2 = wr[2], p3 = wr[3];
            unsigned long long w[8] = { p0.x, p0.y, p1.x, p1.y, p2.x, p2.y, p3.x, p3.y };
            #pragma unroll
            for (int i = 0; i < 4; i++) {
                unsigned long long xs2 = pack2(hs[i][kk], hs[i][kk]);
                #pragma unroll
                for (int j = 0; j < 8; j++) ffma2(acc[i][j], xs2, w[j]);
            }
        }
    }
    #pragma unroll
    for (int i = 0; i < 4; i++) {
        ulonglong2* dst = (ulonglong2*)(g_HA + (long)(r0 + i) * HID + cb);
        #pragma unroll
        for (int j = 0; j < 4; j++)
            dst[j] = make_ulonglong2(acc[i][2 * j], acc[i][2 * j + 1]);
    }
}

// h2 = relu(AG + b2); out = h2 @ Wout + bout : thread per row
__global__ void k_out(const float* __restrict__ b2, const float* __restrict__ Wout,
                      const float* __restrict__ bout, float* __restrict__ out) {
    __shared__ float Ws[HID * TOUT];
    __shared__ float bs[HID];
    __shared__ float bo[TOUT];
    for (int i = threadIdx.x; i < HID * TOUT; i += blockDim.x) Ws[i] = Wout[i];
    if (threadIdx.x < HID)  bs[threadIdx.x] = b2[threadIdx.x];
    if (threadIdx.x < TOUT) bo[threadIdx.x] = bout[threadIdx.x];
    __syncthreads();
    int row = blockIdx.x * blockDim.x + threadIdx.x;
    if (row >= NN) return;
    const float4* ar = (const float4*)(g_AG + (long)row * HID);
    const float4* b4 = (const float4*)bs;
    float acc[TOUT];
    #pragma unroll
    for (int j = 0; j < TOUT; j++) acc[j] = bo[j];
    #pragma unroll 2
    for (int k4 = 0; k4 < HID / 4; k4++) {
        float4 av = ar[k4];
        float4 bv = b4[k4];
        float hs[4] = { fmaxf(av.x + bv.x, 0.f), fmaxf(av.y + bv.y, 0.f),
                        fmaxf(av.z + bv.z, 0.f), fmaxf(av.w + bv.w, 0.f) };
        #pragma unroll
        for (int kk = 0; kk < 4; kk++) {
            float xs = hs[kk];
            const float* wr = &Ws[(k4 * 4 + kk) * TOUT];
            #pragma unroll
            for (int j = 0; j < TOUT; j++) acc[j] += xs * wr[j];
        }
    }
    float* o = out + (long)row * TOUT;
    #pragma unroll
    for (int j = 0; j < TOUT; j++) o[j] = acc[j];
}

// ---------------- launch ----------------
extern "C" void kernel_launch(void* const* d_in, const int* in_sizes, int n_in,
                              void* d_out, int out_size) {
    const float* x    = (const float*)d_in[0];
    const int*   ei   = (const int*)d_in[1];
    const float* et   = (const float*)d_in[2];
    const float* W1   = (const float*)d_in[3];
    const float* b1   = (const float*)d_in[4];
    const float* W2   = (const float*)d_in[5];
    const float* b2   = (const float*)d_in[6];
    const float* Wout = (const float*)d_in[7];
    const float* bout = (const float*)d_in[8];
    float*       out  = (float*)d_out;

    const int TB = 256;
    const int GEMMB = (NG * 4 + TB - 1) / TB;   // 4 slices per row group
    k_detect_zero<<<NB, TB>>>(ei);
    k_max1<<<MAXB, TB>>>(et);
    k_max2<<<1, MAXB>>>();
    k_gemm1<<<GEMMB, TB>>>(x, W1);       // slot 4: profiled by ncu sampler
    k_decay_deg<<<(NE + TB - 1) / TB, TB>>>(ei, et);
    k_dinv <<<NB, TB>>>();
    k_ew_deg2<<<(NE + TB - 1) / TB, TB>>>();
    k_scanA<<<NB, TB>>>();
    k_scanB<<<1, 512>>>();
    k_scanC<<<NB, TB>>>();               // also finalizes dinv2/nself
    k_fill <<<(NE + TB - 1) / TB, TB>>>();

    k_spmm_csr<<<(NN * 32 + TB - 1) / TB, TB>>>();
    k_layer1<<<GEMMB, TB>>>(b1, W2);
    k_spmm_csr<<<(NN * 32 + TB - 1) / TB, TB>>>();
    k_out<<<NB, TB>>>(b2, Wout, bout, out);
}

// round 12
// speedup vs baseline: 1.3135x; 1.0614x over previous
#include <cuda_runtime.h>

// ---------------- problem constants (fixed shapes) ----------------
constexpr int   NN   = 100000;   // nodes
constexpr int   NE   = 1600000;  // edges
constexpr int   FIN  = 128;
constexpr int   HID  = 64;
constexpr int   TOUT = 10;
constexpr int   NB   = (NN + 255) / 256;   // 391 node blocks
constexpr int   NG   = NN / 4;             // 25000 row groups of 4
#define ALPHA 0.1f

// ---------------- f32x2 packed math helpers ----------------
__device__ __forceinline__ unsigned long long pack2(float x, float y) {
    unsigned long long r;
    asm("mov.b64 %0, {%1, %2};" : "=l"(r) : "f"(x), "f"(y));
    return r;
}
__device__ __forceinline__ void ffma2(unsigned long long& d,
                                      unsigned long long a, unsigned long long b) {
    asm("fma.rn.f32x2 %0, %1, %2, %0;" : "+l"(d) : "l"(a), "l"(b));
}

// ---------------- device scratch (no allocations allowed) ----------------
__device__ int   g_is64;           // 1 if edge_index buffer is int64
__device__ int2  g_edge[NE];       // (row, col) as int32
__device__ float g_w[NE];          // decay -> ew (in place)
__device__ float g_deg[NN];        // out-degree (decay-weighted)
__device__ float g_dinv2[NN];      // deg2 accumulator, then dinv2
__device__ float g_nself[NN];      // self-loop norm = dinv2^2
__device__ int   g_cnt[NN];        // in-degree counts (by col)
__device__ int   g_bsum[NB];       // scan: per-block sums
__device__ int   g_ptr[NN + 1];    // CSR row pointers (by col)
__device__ int   g_pos[NN];        // fill cursors
__device__ int2  g_csre[NE];       // CSR edge records {src, norm bits}
__device__ float g_HA[NN * HID];   // H0, later overwritten by H1b
__device__ float g_AG[NN * HID];   // aggregation output (written once/node)

// ---------------- kernels ----------------

// detect dtype + zero per-node accumulators (fused)
__global__ void k_detect_zero(const int* __restrict__ ei32) {
    int i = blockIdx.x * blockDim.x + threadIdx.x;
    if (i == 0) {
        int odd_or = 0;
        #pragma unroll
        for (int k = 1; k < 64; k += 2) odd_or |= ei32[k];
        g_is64 = (odd_or == 0) ? 1 : 0;
    }
    if (i < NN) { g_deg[i] = 0.f; g_dinv2[i] = 0.f; g_cnt[i] = 0; }
}

// decay = exp(alpha*t)  [the exp(-alpha*tmax) factor cancels in the symmetric
// normalization, so tmax is never needed]; deg[row] += decay; cnt[col]++
__global__ void k_decay_deg(const int* __restrict__ ei, const float* __restrict__ t) {
    int e = blockIdx.x * blockDim.x + threadIdx.x;
    if (e >= NE) return;
    int r, c;
    if (g_is64) {
        const long long* e64 = (const long long*)ei;
        r = (int)e64[e];
        c = (int)e64[NE + e];
    } else {
        r = ei[e];
        c = ei[NE + e];
    }
    g_edge[e] = make_int2(r, c);
    float d = expf(ALPHA * t[e]);
    g_w[e] = d;
    atomicAdd(&g_deg[r], d);
    atomicAdd(&g_cnt[c], 1);
}

// ew = dinv[row]*decay*dinv[col] with dinv computed on the fly;
// deg2[col] += ew  (deg2 lives in g_dinv2)
__global__ void k_ew_deg2() {
    int e = blockIdx.x * blockDim.x + threadIdx.x;
    if (e >= NE) return;
    int2 rc = g_edge[e];
    float dr = g_deg[rc.x];
    float dc = g_deg[rc.y];
    float ir = (dr > 0.f) ? rsqrtf(dr) : 0.f;   // dr>0 always (edge from r exists)
    float ic = (dc > 0.f) ? rsqrtf(dc) : 0.f;   // c may have no out-edges
    float ew = ir * g_w[e] * ic;
    g_w[e] = ew;
    atomicAdd(&g_dinv2[rc.y], ew);
}

// ---- scan phase A: per-block sums of g_cnt ----
__global__ void k_scanA() {
    __shared__ int sm[8];
    int i = blockIdx.x * blockDim.x + threadIdx.x;
    int v = (i < NN) ? g_cnt[i] : 0;
    #pragma unroll
    for (int o = 16; o; o >>= 1) v += __shfl_xor_sync(0xffffffffu, v, o);
    if ((threadIdx.x & 31) == 0) sm[threadIdx.x >> 5] = v;
    __syncthreads();
    if (threadIdx.x < 8) {
        v = sm[threadIdx.x];
        #pragma unroll
        for (int o = 4; o; o >>= 1) v += __shfl_xor_sync(0xffu, v, o);
        if (threadIdx.x == 0) g_bsum[blockIdx.x] = v;
    }
}

// ---- scan phase C (fused with B): each block reduces its bsum prefix,
// then scans its own 256 counts; also finalizes dinv2/nself ----
__global__ void k_scanC() {
    __shared__ int ws[8];
    __shared__ int sbase;
    int t = threadIdx.x, lane = t & 31, wid = t >> 5;
    int bid = blockIdx.x;

    // block offset = sum_{j < bid} g_bsum[j]
    int off = 0;
    for (int j = t; j < bid; j += 256) off += g_bsum[j];
    #pragma unroll
    for (int o = 16; o; o >>= 1) off += __shfl_xor_sync(0xffffffffu, off, o);
    if (lane == 0) ws[wid] = off;
    __syncthreads();
    if (t == 0) {
        int b = 0;
        #pragma unroll
        for (int j = 0; j < 8; j++) b += ws[j];
        sbase = b;
    }
    __syncthreads();
    int base = sbase;
    __syncthreads();   // ws reused below

    // intra-block exclusive scan of counts
    int i = bid * 256 + t;
    int c = (i < NN) ? g_cnt[i] : 0;
    int inc = c;
    #pragma unroll
    for (int o = 1; o < 32; o <<= 1) {
        int u = __shfl_up_sync(0xffffffffu, inc, o);
        if (lane >= o) inc += u;
    }
    if (lane == 31) ws[wid] = inc;
    __syncthreads();
    if (wid == 0 && lane < 8) {
        int w = ws[lane];
        #pragma unroll
        for (int o = 1; o < 8; o <<= 1) {
            int u = __shfl_up_sync(0xffu, w, o);
            if (lane >= o) w += u;
        }
        ws[lane] = w;
    }
    __syncthreads();
    int ex = inc - c + (wid ? ws[wid - 1] : 0) + base;
    if (i < NN) {
        g_ptr[i] = ex;
        g_pos[i] = ex;
        float d2 = g_dinv2[i] + 1.0f;     // + self loop weight 1
        float di = rsqrtf(d2);
        g_dinv2[i] = di;
        g_nself[i] = di * di;
    }
    if (i == NN - 1) g_ptr[NN] = ex + c;
}

__global__ void k_fill() {
    int e = blockIdx.x * blockDim.x + threadIdx.x;
    if (e >= NE) return;
    int2 rc = g_edge[e];
    float nm = g_dinv2[rc.x] * g_w[e] * g_dinv2[rc.y];
    int p = atomicAdd(&g_pos[rc.y], 1);
    g_csre[p] = make_int2(rc.x, __float_as_int(nm));
}

// HA = x @ W1: thread computes 4 rows x 16 cols, f32x2 packed FMA
__global__ void __launch_bounds__(256, 2)
k_gemm1(const float* __restrict__ x, const float* __restrict__ W1) {
    __shared__ float Ws[FIN * HID]; // 32 KB
    {
        const float4* w4 = (const float4*)W1;
        float4* s4 = (float4*)Ws;
        for (int i = threadIdx.x; i < FIN * HID / 4; i += blockDim.x) s4[i] = w4[i];
    }
    __syncthreads();
    int gt    = blockIdx.x * blockDim.x + threadIdx.x;
    int grp   = gt >> 2;          // row group (4 rows)
    int slice = gt & 3;           // 16-col slice
    if (grp >= NG) return;
    int r0 = grp * 4;
    const float4* xr0 = (const float4*)(x + (long)(r0 + 0) * FIN);
    const float4* xr1 = (const float4*)(x + (long)(r0 + 1) * FIN);
    const float4* xr2 = (const float4*)(x + (long)(r0 + 2) * FIN);
    const float4* xr3 = (const float4*)(x + (long)(r0 + 3) * FIN);
    unsigned long long acc[4][8];   // 4 rows x 8 f32x2 pairs (16 cols)
    #pragma unroll
    for (int i = 0; i < 4; i++)
        #pragma unroll
        for (int j = 0; j < 8; j++) acc[i][j] = 0ull;
    const int cb = slice * 16;
    #pragma unroll 2
    for (int k4 = 0; k4 < FIN / 4; k4++) {
        float4 xv[4] = { xr0[k4], xr1[k4], xr2[k4], xr3[k4] };
        #pragma unroll
        for (int kk = 0; kk < 4; kk++) {
            const ulonglong2* wr = (const ulonglong2*)&Ws[(k4 * 4 + kk) * HID + cb];
            ulonglong2 p0 = wr[0], p1 = wr[1], p2 = wr[2], p3 = wr[3];
            unsigned long long w[8] = { p0.x, p0.y, p1.x, p1.y, p2.x, p2.y, p3.x, p3.y };
            #pragma unroll
            for (int i = 0; i < 4; i++) {
                float xs = (kk == 0) ? xv[i].x : (kk == 1) ? xv[i].y
                         : (kk == 2) ? xv[i].z : xv[i].w;
                unsigned long long xs2 = pack2(xs, xs);
                #pragma unroll
                for (int j = 0; j < 8; j++) ffma2(acc[i][j], xs2, w[j]);
            }
        }
    }
    #pragma unroll
    for (int i = 0; i < 4; i++) {
        ulonglong2* dst = (ulonglong2*)(g_HA + (long)(r0 + i) * HID + cb);
        #pragma unroll
        for (int j = 0; j < 4; j++)
            dst[j] = make_ulonglong2(acc[i][2 * j], acc[i][2 * j + 1]);
    }
}

// gather-SpMM: warp per destination node, self-loop folded in, x4 unrolled
__global__ void k_spmm_csr() {
    int i = (blockIdx.x * blockDim.x + threadIdx.x) >> 5;
    if (i >= NN) return;
    int lane = threadIdx.x & 31;
    int beg = g_ptr[i], end = g_ptr[i + 1];
    float  ns = g_nself[i];
    float2 h  = ((const float2*)(g_HA + (long)i * HID))[lane];
    float a0 = ns * h.x, a1 = ns * h.y;
    int e = beg;
    for (; e + 4 <= end; e += 4) {
        int2 r0 = g_csre[e + 0];
        int2 r1 = g_csre[e + 1];
        int2 r2 = g_csre[e + 2];
        int2 r3 = g_csre[e + 3];
        float2 v0 = ((const float2*)(g_HA + (long)r0.x * HID))[lane];
        float2 v1 = ((const float2*)(g_HA + (long)r1.x * HID))[lane];
        float2 v2 = ((const float2*)(g_HA + (long)r2.x * HID))[lane];
        float2 v3 = ((const float2*)(g_HA + (long)r3.x * HID))[lane];
        float n0 = __int_as_float(r0.y), n1 = __int_as_float(r1.y);
        float n2 = __int_as_float(r2.y), n3 = __int_as_float(r3.y);
        a0 += n0 * v0.x; a1 += n0 * v0.y;
        a0 += n1 * v1.x; a1 += n1 * v1.y;
        a0 += n2 * v2.x; a1 += n2 * v2.y;
        a0 += n3 * v3.x; a1 += n3 * v3.y;
    }
    for (; e < end; e++) {
        int2  rec = g_csre[e];
        float nm  = __int_as_float(rec.y);
        float2 v  = ((const float2*)(g_HA + (long)rec.x * HID))[lane];
        a0 += nm * v.x;
        a1 += nm * v.y;
    }
    ((float2*)(g_AG + (long)i * HID))[lane] = make_float2(a0, a1);
}

// h1 = relu(AG + b1); HA <- h1 @ W2 : 4 rows x 16 cols, f32x2 packed FMA
__global__ void __launch_bounds__(256, 2)
k_layer1(const float* __restrict__ b1, const float* __restrict__ W2) {
    __shared__ float Ws[HID * HID]; // 16 KB
    __shared__ float bs[HID];
    {
        const float4* w4 = (const float4*)W2;
        float4* s4 = (float4*)Ws;
        for (int i = threadIdx.x; i < HID * HID / 4; i += blockDim.x) s4[i] = w4[i];
        if (threadIdx.x < HID) bs[threadIdx.x] = b1[threadIdx.x];
    }
    __syncthreads();
    int gt    = blockIdx.x * blockDim.x + threadIdx.x;
    int grp   = gt >> 2;
    int slice = gt & 3;
    if (grp >= NG) return;
    int r0 = grp * 4;
    const float4* a0p = (const float4*)(g_AG + (long)(r0 + 0) * HID);
    const float4* a1p = (const float4*)(g_AG + (long)(r0 + 1) * HID);
    const float4* a2p = (const float4*)(g_AG + (long)(r0 + 2) * HID);
    const float4* a3p = (const float4*)(g_AG + (long)(r0 + 3) * HID);
    const float4* b4  = (const float4*)bs;
    unsigned long long acc[4][8];
    #pragma unroll
    for (int i = 0; i < 4; i++)
        #pragma unroll
        for (int j = 0; j < 8; j++) acc[i][j] = 0ull;
    const int cb = slice * 16;
    #pragma unroll 2
    for (int k4 = 0; k4 < HID / 4; k4++) {
        float4 bv = b4[k4];
        float4 av[4] = { a0p[k4], a1p[k4], a2p[k4], a3p[k4] };
        float hs[4][4];
        #pragma unroll
        for (int i = 0; i < 4; i++) {
            hs[i][0] = fmaxf(av[i].x + bv.x, 0.f);
            hs[i][1] = fmaxf(av[i].y + bv.y, 0.f);
            hs[i][2] = fmaxf(av[i].z + bv.z, 0.f);
            hs[i][3] = fmaxf(av[i].w + bv.w, 0.f);
        }
        #pragma unroll
        for (int kk = 0; kk < 4; kk++) {
            const ulonglong2* wr = (const ulonglong2*)&Ws[(k4 * 4 + kk) * HID + cb];
            ulonglong2 p0 = wr[0], p1 = wr[1], p2 = wr[2], p3 = wr[3];
            unsigned long long w[8] = { p0.x, p0.y, p1.x, p1.y, p2.x, p2.y, p3.x, p3.y };
            #pragma unroll
            for (int i = 0; i < 4; i++) {
                unsigned long long xs2 = pack2(hs[i][kk], hs[i][kk]);
                #pragma unroll
                for (int j = 0; j < 8; j++) ffma2(acc[i][j], xs2, w[j]);
            }
        }
    }
    #pragma unroll
    for (int i = 0; i < 4; i++) {
        ulonglong2* dst = (ulonglong2*)(g_HA + (long)(r0 + i) * HID + cb);
        #pragma unroll
        for (int j = 0; j < 4; j++)
            dst[j] = make_ulonglong2(acc[i][2 * j], acc[i][2 * j + 1]);
    }
}

// h2 = relu(AG + b2); out = h2 @ Wout + bout : thread per row
__global__ void k_out(const float* __restrict__ b2, const float* __restrict__ Wout,
                      const float* __restrict__ bout, float* __restrict__ out) {
    __shared__ float Ws[HID * TOUT];
    __shared__ float bs[HID];
    __shared__ float bo[TOUT];
    for (int i = threadIdx.x; i < HID * TOUT; i += blockDim.x) Ws[i] = Wout[i];
    if (threadIdx.x < HID)  bs[threadIdx.x] = b2[threadIdx.x];
    if (threadIdx.x < TOUT) bo[threadIdx.x] = bout[threadIdx.x];
    __syncthreads();
    int row = blockIdx.x * blockDim.x + threadIdx.x;
    if (row >= NN) return;
    const float4* ar = (const float4*)(g_AG + (long)row * HID);
    const float4* b4 = (const float4*)bs;
    float acc[TOUT];
    #pragma unroll
    for (int j = 0; j < TOUT; j++) acc[j] = bo[j];
    #pragma unroll 2
    for (int k4 = 0; k4 < HID / 4; k4++) {
        float4 av = ar[k4];
        float4 bv = b4[k4];
        float hs[4] = { fmaxf(av.x + bv.x, 0.f), fmaxf(av.y + bv.y, 0.f),
                        fmaxf(av.z + bv.z, 0.f), fmaxf(av.w + bv.w, 0.f) };
        #pragma unroll
        for (int kk = 0; kk < 4; kk++) {
            float xs = hs[kk];
            const float* wr = &Ws[(k4 * 4 + kk) * TOUT];
            #pragma unroll
            for (int j = 0; j < TOUT; j++) acc[j] += xs * wr[j];
        }
    }
    float* o = out + (long)row * TOUT;
    #pragma unroll
    for (int j = 0; j < TOUT; j++) o[j] = acc[j];
}

// ---------------- launch ----------------
extern "C" void kernel_launch(void* const* d_in, const int* in_sizes, int n_in,
                              void* d_out, int out_size) {
    const float* x    = (const float*)d_in[0];
    const int*   ei   = (const int*)d_in[1];
    const float* et   = (const float*)d_in[2];
    const float* W1   = (const float*)d_in[3];
    const float* b1   = (const float*)d_in[4];
    const float* W2   = (const float*)d_in[5];
    const float* b2   = (const float*)d_in[6];
    const float* Wout = (const float*)d_in[7];
    const float* bout = (const float*)d_in[8];
    float*       out  = (float*)d_out;

    const int TB = 256;
    const int GEMMB = (NG * 4 + TB - 1) / TB;   // 4 slices per row group
    k_detect_zero<<<NB, TB>>>(ei);
    k_decay_deg<<<(NE + TB - 1) / TB, TB>>>(ei, et);
    k_ew_deg2<<<(NE + TB - 1) / TB, TB>>>();
    k_gemm1<<<GEMMB, TB>>>(x, W1);       // slot 4: profiled by ncu sampler
    k_scanA<<<NB, TB>>>();
    k_scanC<<<NB, TB>>>();               // fused scanB + dinv2/nself finalize
    k_fill <<<(NE + TB - 1) / TB, TB>>>();

    k_spmm_csr<<<(NN * 32 + TB - 1) / TB, TB>>>();
    k_layer1<<<GEMMB, TB>>>(b1, W2);
    k_spmm_csr<<<(NN * 32 + TB - 1) / TB, TB>>>();
    k_out<<<NB, TB>>>(b2, Wout, bout, out);
}

// round 13
// speedup vs baseline: 1.3860x; 1.0552x over previous
#include <cuda_runtime.h>

// ---------------- problem constants (fixed shapes) ----------------
constexpr int   NN   = 100000;   // nodes
constexpr int   NE   = 1600000;  // edges
constexpr int   FIN  = 128;
constexpr int   HID  = 64;
constexpr int   TOUT = 10;
constexpr int   NB   = (NN + 255) / 256;   // 391 node blocks
constexpr int   NG   = NN / 4;             // 25000 row groups of 4
#define ALPHA 0.1f

// ---------------- f32x2 packed math helpers ----------------
__device__ __forceinline__ unsigned long long pack2(float x, float y) {
    unsigned long long r;
    asm("mov.b64 %0, {%1, %2};" : "=l"(r) : "f"(x), "f"(y));
    return r;
}
__device__ __forceinline__ void ffma2(unsigned long long& d,
                                      unsigned long long a, unsigned long long b) {
    asm("fma.rn.f32x2 %0, %1, %2, %0;" : "+l"(d) : "l"(a), "l"(b));
}

// ---------------- device scratch (no allocations allowed) ----------------
__device__ int   g_is64;           // 1 if edge_index buffer is int64
__device__ int2  g_edge[NE];       // (row, col) as int32
__device__ float g_w[NE];          // decay -> ew (in place)
__device__ float g_deg[NN];        // out-degree (decay-weighted)
__device__ float g_dinv2[NN];      // deg2 accumulator, then dinv2
__device__ float g_nself[NN];      // self-loop norm = dinv2^2
__device__ int   g_cnt[NN];        // in-degree counts (by col)
__device__ int   g_bsum[NB];       // scan: per-block sums
__device__ int   g_ptr[NN + 1];    // CSR row pointers (by col)
__device__ int   g_pos[NN];        // fill cursors
__device__ int2  g_csre[NE];       // CSR edge records {src, norm bits}
__device__ float g_HA[NN * HID];   // H0, later overwritten by H1b
__device__ float g_AG[NN * HID];   // aggregation output (written once/node)

// ---------------- kernels ----------------

// detect dtype + zero per-node accumulators (fused)
__global__ void k_detect_zero(const int* __restrict__ ei32) {
    int i = blockIdx.x * blockDim.x + threadIdx.x;
    if (i == 0) {
        int odd_or = 0;
        #pragma unroll
        for (int k = 1; k < 64; k += 2) odd_or |= ei32[k];
        g_is64 = (odd_or == 0) ? 1 : 0;
    }
    if (i < NN) { g_deg[i] = 0.f; g_dinv2[i] = 0.f; g_cnt[i] = 0; }
}

// decay = exp(alpha*t)  [exp(-alpha*tmax) cancels in the symmetric norm];
// deg[row] += decay; cnt[col]++
__global__ void k_decay_deg(const int* __restrict__ ei, const float* __restrict__ t) {
    int e = blockIdx.x * blockDim.x + threadIdx.x;
    if (e >= NE) return;
    int r, c;
    if (g_is64) {
        const long long* e64 = (const long long*)ei;
        r = (int)e64[e];
        c = (int)e64[NE + e];
    } else {
        r = ei[e];
        c = ei[NE + e];
    }
    g_edge[e] = make_int2(r, c);
    float d = expf(ALPHA * t[e]);
    g_w[e] = d;
    atomicAdd(&g_deg[r], d);
    atomicAdd(&g_cnt[c], 1);
}

// ew = dinv[row]*decay*dinv[col] (dinv on the fly); deg2[col] += ew
__global__ void k_ew_deg2() {
    int e = blockIdx.x * blockDim.x + threadIdx.x;
    if (e >= NE) return;
    int2 rc = g_edge[e];
    float dr = g_deg[rc.x];
    float dc = g_deg[rc.y];
    float ir = (dr > 0.f) ? rsqrtf(dr) : 0.f;
    float ic = (dc > 0.f) ? rsqrtf(dc) : 0.f;
    float ew = ir * g_w[e] * ic;
    g_w[e] = ew;
    atomicAdd(&g_dinv2[rc.y], ew);
}

// ---- scan phase A: per-block sums of g_cnt ----
__global__ void k_scanA() {
    __shared__ int sm[8];
    int i = blockIdx.x * blockDim.x + threadIdx.x;
    int v = (i < NN) ? g_cnt[i] : 0;
    #pragma unroll
    for (int o = 16; o; o >>= 1) v += __shfl_xor_sync(0xffffffffu, v, o);
    if ((threadIdx.x & 31) == 0) sm[threadIdx.x >> 5] = v;
    __syncthreads();
    if (threadIdx.x < 8) {
        v = sm[threadIdx.x];
        #pragma unroll
        for (int o = 4; o; o >>= 1) v += __shfl_xor_sync(0xffu, v, o);
        if (threadIdx.x == 0) g_bsum[blockIdx.x] = v;
    }
}

// ---- scan phase C (fused B): block reduces its bsum prefix, scans its 256
// counts; also finalizes dinv2/nself ----
__global__ void k_scanC() {
    __shared__ int ws[8];
    __shared__ int sbase;
    int t = threadIdx.x, lane = t & 31, wid = t >> 5;
    int bid = blockIdx.x;

    int off = 0;
    for (int j = t; j < bid; j += 256) off += g_bsum[j];
    #pragma unroll
    for (int o = 16; o; o >>= 1) off += __shfl_xor_sync(0xffffffffu, off, o);
    if (lane == 0) ws[wid] = off;
    __syncthreads();
    if (t == 0) {
        int b = 0;
        #pragma unroll
        for (int j = 0; j < 8; j++) b += ws[j];
        sbase = b;
    }
    __syncthreads();
    int base = sbase;
    __syncthreads();   // ws reused below

    int i = bid * 256 + t;
    int c = (i < NN) ? g_cnt[i] : 0;
    int inc = c;
    #pragma unroll
    for (int o = 1; o < 32; o <<= 1) {
        int u = __shfl_up_sync(0xffffffffu, inc, o);
        if (lane >= o) inc += u;
    }
    if (lane == 31) ws[wid] = inc;
    __syncthreads();
    if (wid == 0 && lane < 8) {
        int w = ws[lane];
        #pragma unroll
        for (int o = 1; o < 8; o <<= 1) {
            int u = __shfl_up_sync(0xffu, w, o);
            if (lane >= o) w += u;
        }
        ws[lane] = w;
    }
    __syncthreads();
    int ex = inc - c + (wid ? ws[wid - 1] : 0) + base;
    if (i < NN) {
        g_ptr[i] = ex;
        g_pos[i] = ex;
        float d2 = g_dinv2[i] + 1.0f;     // + self loop weight 1
        float di = rsqrtf(d2);
        g_dinv2[i] = di;
        g_nself[i] = di * di;
    }
    if (i == NN - 1) g_ptr[NN] = ex + c;
}

__global__ void k_fill() {
    int e = blockIdx.x * blockDim.x + threadIdx.x;
    if (e >= NE) return;
    int2 rc = g_edge[e];
    float nm = g_dinv2[rc.x] * g_w[e] * g_dinv2[rc.y];
    int p = atomicAdd(&g_pos[rc.y], 1);
    g_csre[p] = make_int2(rc.x, __float_as_int(nm));
}

// HA = x @ W1: thread computes 4 rows x 16 cols, f32x2 packed FMA
__global__ void __launch_bounds__(256, 2)
k_gemm1(const float* __restrict__ x, const float* __restrict__ W1) {
    __shared__ float Ws[FIN * HID]; // 32 KB
    {
        const float4* w4 = (const float4*)W1;
        float4* s4 = (float4*)Ws;
        for (int i = threadIdx.x; i < FIN * HID / 4; i += blockDim.x) s4[i] = w4[i];
    }
    __syncthreads();
    int gt    = blockIdx.x * blockDim.x + threadIdx.x;
    int grp   = gt >> 2;          // row group (4 rows)
    int slice = gt & 3;           // 16-col slice
    if (grp >= NG) return;
    int r0 = grp * 4;
    const float4* xr0 = (const float4*)(x + (long)(r0 + 0) * FIN);
    const float4* xr1 = (const float4*)(x + (long)(r0 + 1) * FIN);
    const float4* xr2 = (const float4*)(x + (long)(r0 + 2) * FIN);
    const float4* xr3 = (const float4*)(x + (long)(r0 + 3) * FIN);
    unsigned long long acc[4][8];   // 4 rows x 8 f32x2 pairs (16 cols)
    #pragma unroll
    for (int i = 0; i < 4; i++)
        #pragma unroll
        for (int j = 0; j < 8; j++) acc[i][j] = 0ull;
    const int cb = slice * 16;
    #pragma unroll 2
    for (int k4 = 0; k4 < FIN / 4; k4++) {
        float4 xv[4] = { xr0[k4], xr1[k4], xr2[k4], xr3[k4] };
        #pragma unroll
        for (int kk = 0; kk < 4; kk++) {
            const ulonglong2* wr = (const ulonglong2*)&Ws[(k4 * 4 + kk) * HID + cb];
            ulonglong2 p0 = wr[0], p1 = wr[1], p2 = wr[2], p3 = wr[3];
            unsigned long long w[8] = { p0.x, p0.y, p1.x, p1.y, p2.x, p2.y, p3.x, p3.y };
            #pragma unroll
            for (int i = 0; i < 4; i++) {
                float xs = (kk == 0) ? xv[i].x : (kk == 1) ? xv[i].y
                         : (kk == 2) ? xv[i].z : xv[i].w;
                unsigned long long xs2 = pack2(xs, xs);
                #pragma unroll
                for (int j = 0; j < 8; j++) ffma2(acc[i][j], xs2, w[j]);
            }
        }
    }
    #pragma unroll
    for (int i = 0; i < 4; i++) {
        ulonglong2* dst = (ulonglong2*)(g_HA + (long)(r0 + i) * HID + cb);
        #pragma unroll
        for (int j = 0; j < 4; j++)
            dst[j] = make_ulonglong2(acc[i][2 * j], acc[i][2 * j + 1]);
    }
}

// gather-SpMM: warp per destination node, self-loop folded in, x4 unrolled
__global__ void k_spmm_csr() {
    int i = (blockIdx.x * blockDim.x + threadIdx.x) >> 5;
    if (i >= NN) return;
    int lane = threadIdx.x & 31;
    int beg = g_ptr[i], end = g_ptr[i + 1];
    float  ns = g_nself[i];
    float2 h  = ((const float2*)(g_HA + (long)i * HID))[lane];
    float a0 = ns * h.x, a1 = ns * h.y;
    int e = beg;
    for (; e + 4 <= end; e += 4) {
        int2 r0 = g_csre[e + 0];
        int2 r1 = g_csre[e + 1];
        int2 r2 = g_csre[e + 2];
        int2 r3 = g_csre[e + 3];
        float2 v0 = ((const float2*)(g_HA + (long)r0.x * HID))[lane];
        float2 v1 = ((const float2*)(g_HA + (long)r1.x * HID))[lane];
        float2 v2 = ((const float2*)(g_HA + (long)r2.x * HID))[lane];
        float2 v3 = ((const float2*)(g_HA + (long)r3.x * HID))[lane];
        float n0 = __int_as_float(r0.y), n1 = __int_as_float(r1.y);
        float n2 = __int_as_float(r2.y), n3 = __int_as_float(r3.y);
        a0 += n0 * v0.x; a1 += n0 * v0.y;
        a0 += n1 * v1.x; a1 += n1 * v1.y;
        a0 += n2 * v2.x; a1 += n2 * v2.y;
        a0 += n3 * v3.x; a1 += n3 * v3.y;
    }
    for (; e < end; e++) {
        int2  rec = g_csre[e];
        float nm  = __int_as_float(rec.y);
        float2 v  = ((const float2*)(g_HA + (long)rec.x * HID))[lane];
        a0 += nm * v.x;
        a1 += nm * v.y;
    }
    ((float2*)(g_AG + (long)i * HID))[lane] = make_float2(a0, a1);
}

// h1 = relu(AG + b1); HA <- h1 @ W2 : 4 rows x 16 cols, f32x2 packed FMA
__global__ void __launch_bounds__(256, 2)
k_layer1(const float* __restrict__ b1, const float* __restrict__ W2) {
    __shared__ float Ws[HID * HID]; // 16 KB
    __shared__ float bs[HID];
    {
        const float4* w4 = (const float4*)W2;
        float4* s4 = (float4*)Ws;
        for (int i = threadIdx.x; i < HID * HID / 4; i += blockDim.x) s4[i] = w4[i];
        if (threadIdx.x < HID) bs[threadIdx.x] = b1[threadIdx.x];
    }
    __syncthreads();
    int gt    = blockIdx.x * blockDim.x + threadIdx.x;
    int grp   = gt >> 2;
    int slice = gt & 3;
    if (grp >= NG) return;
    int r0 = grp * 4;
    const float4* a0p = (const float4*)(g_AG + (long)(r0 + 0) * HID);
    const float4* a1p = (const float4*)(g_AG + (long)(r0 + 1) * HID);
    const float4* a2p = (const float4*)(g_AG + (long)(r0 + 2) * HID);
    const float4* a3p = (const float4*)(g_AG + (long)(r0 + 3) * HID);
    const float4* b4  = (const float4*)bs;
    unsigned long long acc[4][8];
    #pragma unroll
    for (int i = 0; i < 4; i++)
        #pragma unroll
        for (int j = 0; j < 8; j++) acc[i][j] = 0ull;
    const int cb = slice * 16;
    #pragma unroll 2
    for (int k4 = 0; k4 < HID / 4; k4++) {
        float4 bv = b4[k4];
        float4 av[4] = { a0p[k4], a1p[k4], a2p[k4], a3p[k4] };
        float hs[4][4];
        #pragma unroll
        for (int i = 0; i < 4; i++) {
            hs[i][0] = fmaxf(av[i].x + bv.x, 0.f);
            hs[i][1] = fmaxf(av[i].y + bv.y, 0.f);
            hs[i][2] = fmaxf(av[i].z + bv.z, 0.f);
            hs[i][3] = fmaxf(av[i].w + bv.w, 0.f);
        }
        #pragma unroll
        for (int kk = 0; kk < 4; kk++) {
            const ulonglong2* wr = (const ulonglong2*)&Ws[(k4 * 4 + kk) * HID + cb];
            ulonglong2 p0 = wr[0], p1 = wr[1], p2 = wr[2], p3 = wr[3];
            unsigned long long w[8] = { p0.x, p0.y, p1.x, p1.y, p2.x, p2.y, p3.x, p3.y };
            #pragma unroll
            for (int i = 0; i < 4; i++) {
                unsigned long long xs2 = pack2(hs[i][kk], hs[i][kk]);
                #pragma unroll
                for (int j = 0; j < 8; j++) ffma2(acc[i][j], xs2, w[j]);
            }
        }
    }
    #pragma unroll
    for (int i = 0; i < 4; i++) {
        ulonglong2* dst = (ulonglong2*)(g_HA + (long)(r0 + i) * HID + cb);
        #pragma unroll
        for (int j = 0; j < 4; j++)
            dst[j] = make_ulonglong2(acc[i][2 * j], acc[i][2 * j + 1]);
    }
}

// h2 = relu(AG + b2); out = h2 @ Wout + bout : thread per row
__global__ void k_out(const float* __restrict__ b2, const float* __restrict__ Wout,
                      const float* __restrict__ bout, float* __restrict__ out) {
    __shared__ float Ws[HID * TOUT];
    __shared__ float bs[HID];
    __shared__ float bo[TOUT];
    for (int i = threadIdx.x; i < HID * TOUT; i += blockDim.x) Ws[i] = Wout[i];
    if (threadIdx.x < HID)  bs[threadIdx.x] = b2[threadIdx.x];
    if (threadIdx.x < TOUT) bo[threadIdx.x] = bout[threadIdx.x];
    __syncthreads();
    int row = blockIdx.x * blockDim.x + threadIdx.x;
    if (row >= NN) return;
    const float4* ar = (const float4*)(g_AG + (long)row * HID);
    const float4* b4 = (const float4*)bs;
    float acc[TOUT];
    #pragma unroll
    for (int j = 0; j < TOUT; j++) acc[j] = bo[j];
    #pragma unroll 2
    for (int k4 = 0; k4 < HID / 4; k4++) {
        float4 av = ar[k4];
        float4 bv = b4[k4];
        float hs[4] = { fmaxf(av.x + bv.x, 0.f), fmaxf(av.y + bv.y, 0.f),
                        fmaxf(av.z + bv.z, 0.f), fmaxf(av.w + bv.w, 0.f) };
        #pragma unroll
        for (int kk = 0; kk < 4; kk++) {
            float xs = hs[kk];
            const float* wr = &Ws[(k4 * 4 + kk) * TOUT];
            #pragma unroll
            for (int j = 0; j < TOUT; j++) acc[j] += xs * wr[j];
        }
    }
    float* o = out + (long)row * TOUT;
    #pragma unroll
    for (int j = 0; j < TOUT; j++) o[j] = acc[j];
}

// ---------------- launch ----------------
extern "C" void kernel_launch(void* const* d_in, const int* in_sizes, int n_in,
                              void* d_out, int out_size) {
    const float* x    = (const float*)d_in[0];
    const int*   ei   = (const int*)d_in[1];
    const float* et   = (const float*)d_in[2];
    const float* W1   = (const float*)d_in[3];
    const float* b1   = (const float*)d_in[4];
    const float* W2   = (const float*)d_in[5];
    const float* b2   = (const float*)d_in[6];
    const float* Wout = (const float*)d_in[7];
    const float* bout = (const float*)d_in[8];
    float*       out  = (float*)d_out;

    const int TB = 256;
    const int GEMMB = (NG * 4 + TB - 1) / TB;

    // Side stream for gemm1 (independent of edge preprocessing).
    // Created per call (kernel_launch runs only for correctness + capture);
    // fork/join via events is the capture-legal multi-stream pattern.
    cudaStream_t s2;
    cudaEvent_t  eFork, eJoin;
    cudaStreamCreateWithFlags(&s2, cudaStreamNonBlocking);
    cudaEventCreateWithFlags(&eFork, cudaEventDisableTiming);
    cudaEventCreateWithFlags(&eJoin, cudaEventDisableTiming);

    // fork: gemm1 runs concurrently with the whole edge-preprocessing chain
    cudaEventRecord(eFork, 0);
    cudaStreamWaitEvent(s2, eFork, 0);
    k_gemm1<<<GEMMB, TB, 0, s2>>>(x, W1);
    cudaEventRecord(eJoin, s2);

    // main stream: edge preprocessing -> CSR
    k_detect_zero<<<NB, TB>>>(ei);
    k_decay_deg<<<(NE + TB - 1) / TB, TB>>>(ei, et);
    k_ew_deg2<<<(NE + TB - 1) / TB, TB>>>();
    k_scanA<<<NB, TB>>>();
    k_scanC<<<NB, TB>>>();
    k_fill <<<(NE + TB - 1) / TB, TB>>>();

    // join: spmm needs both HA (gemm1) and CSR (fill)
    cudaStreamWaitEvent(0, eJoin, 0);

    k_spmm_csr<<<(NN * 32 + TB - 1) / TB, TB>>>();
    k_layer1<<<GEMMB, TB>>>(b1, W2);
    k_spmm_csr<<<(NN * 32 + TB - 1) / TB, TB>>>();
    k_out<<<NB, TB>>>(b2, Wout, bout, out);
}

// round 14
// speedup vs baseline: 1.3971x; 1.0080x over previous
#include <cuda_runtime.h>

// ---------------- problem constants (fixed shapes) ----------------
constexpr int   NN   = 100000;   // nodes
constexpr int   NE   = 1600000;  // edges
constexpr int   FIN  = 128;
constexpr int   HID  = 64;
constexpr int   TOUT = 10;
constexpr int   NB   = (NN + 255) / 256;   // 391 node blocks
constexpr int   NG   = NN / 4;             // 25000 row groups of 4
constexpr int   NSM  = 148;                // sm_100a SM count
#define ALPHA 0.1f

// ---------------- f32x2 packed math helpers ----------------
__device__ __forceinline__ unsigned long long pack2(float x, float y) {
    unsigned long long r;
    asm("mov.b64 %0, {%1, %2};" : "=l"(r) : "f"(x), "f"(y));
    return r;
}
__device__ __forceinline__ void ffma2(unsigned long long& d,
                                      unsigned long long a, unsigned long long b) {
    asm("fma.rn.f32x2 %0, %1, %2, %0;" : "+l"(d) : "l"(a), "l"(b));
}

// ---------------- device scratch (no allocations allowed) ----------------
__device__ int   g_is64;           // 1 if edge_index buffer is int64
__device__ int2  g_edge[NE];       // (row, col) as int32
__device__ float g_w[NE];          // decay -> ew (in place)
__device__ float g_deg[NN];        // out-degree (decay-weighted)
__device__ float g_dinv2[NN];      // deg2 accumulator, then dinv2
__device__ float g_nself[NN];      // self-loop norm = dinv2^2
__device__ int   g_cnt[NN];        // in-degree counts (by col)
__device__ int   g_bsum[NB];       // scan: per-block sums
__device__ int   g_ptr[NN + 1];    // CSR row pointers (by col)
__device__ int   g_pos[NN];        // fill cursors
__device__ int2  g_csre[NE];       // CSR edge records {src, norm bits}
__device__ float g_HA[NN * HID];   // H0, later overwritten by H1b
__device__ float g_AG[NN * HID];   // aggregation output (written once/node)

// ---------------- kernels ----------------

__global__ void k_detect_zero(const int* __restrict__ ei32) {
    int i = blockIdx.x * blockDim.x + threadIdx.x;
    if (i == 0) {
        int odd_or = 0;
        #pragma unroll
        for (int k = 1; k < 64; k += 2) odd_or |= ei32[k];
        g_is64 = (odd_or == 0) ? 1 : 0;
    }
    if (i < NN) { g_deg[i] = 0.f; g_dinv2[i] = 0.f; g_cnt[i] = 0; }
}

// decay = exp(alpha*t)  [exp(-alpha*tmax) cancels in the symmetric norm];
// deg[row] += decay; cnt[col]++
__global__ void k_decay_deg(const int* __restrict__ ei, const float* __restrict__ t) {
    int e = blockIdx.x * blockDim.x + threadIdx.x;
    if (e >= NE) return;
    int r, c;
    if (g_is64) {
        const long long* e64 = (const long long*)ei;
        r = (int)e64[e];
        c = (int)e64[NE + e];
    } else {
        r = ei[e];
        c = ei[NE + e];
    }
    g_edge[e] = make_int2(r, c);
    float d = expf(ALPHA * t[e]);
    g_w[e] = d;
    atomicAdd(&g_deg[r], d);
    atomicAdd(&g_cnt[c], 1);
}

// ew = dinv[row]*decay*dinv[col] (dinv on the fly); deg2[col] += ew
__global__ void k_ew_deg2() {
    int e = blockIdx.x * blockDim.x + threadIdx.x;
    if (e >= NE) return;
    int2 rc = g_edge[e];
    float dr = g_deg[rc.x];
    float dc = g_deg[rc.y];
    float ir = (dr > 0.f) ? rsqrtf(dr) : 0.f;
    float ic = (dc > 0.f) ? rsqrtf(dc) : 0.f;
    float ew = ir * g_w[e] * ic;
    g_w[e] = ew;
    atomicAdd(&g_dinv2[rc.y], ew);
}

// ---- scan phase A: per-block sums of g_cnt ----
__global__ void k_scanA() {
    __shared__ int sm[8];
    int i = blockIdx.x * blockDim.x + threadIdx.x;
    int v = (i < NN) ? g_cnt[i] : 0;
    #pragma unroll
    for (int o = 16; o; o >>= 1) v += __shfl_xor_sync(0xffffffffu, v, o);
    if ((threadIdx.x & 31) == 0) sm[threadIdx.x >> 5] = v;
    __syncthreads();
    if (threadIdx.x < 8) {
        v = sm[threadIdx.x];
        #pragma unroll
        for (int o = 4; o; o >>= 1) v += __shfl_xor_sync(0xffu, v, o);
        if (threadIdx.x == 0) g_bsum[blockIdx.x] = v;
    }
}

// ---- scan phase C (fused B): block reduces its bsum prefix, scans its 256
// counts; also finalizes dinv2/nself ----
__global__ void k_scanC() {
    __shared__ int ws[8];
    __shared__ int sbase;
    int t = threadIdx.x, lane = t & 31, wid = t >> 5;
    int bid = blockIdx.x;

    int off = 0;
    for (int j = t; j < bid; j += 256) off += g_bsum[j];
    #pragma unroll
    for (int o = 16; o; o >>= 1) off += __shfl_xor_sync(0xffffffffu, off, o);
    if (lane == 0) ws[wid] = off;
    __syncthreads();
    if (t == 0) {
        int b = 0;
        #pragma unroll
        for (int j = 0; j < 8; j++) b += ws[j];
        sbase = b;
    }
    __syncthreads();
    int base = sbase;
    __syncthreads();   // ws reused below

    int i = bid * 256 + t;
    int c = (i < NN) ? g_cnt[i] : 0;
    int inc = c;
    #pragma unroll
    for (int o = 1; o < 32; o <<= 1) {
        int u = __shfl_up_sync(0xffffffffu, inc, o);
        if (lane >= o) inc += u;
    }
    if (lane == 31) ws[wid] = inc;
    __syncthreads();
    if (wid == 0 && lane < 8) {
        int w = ws[lane];
        #pragma unroll
        for (int o = 1; o < 8; o <<= 1) {
            int u = __shfl_up_sync(0xffu, w, o);
            if (lane >= o) w += u;
        }
        ws[lane] = w;
    }
    __syncthreads();
    int ex = inc - c + (wid ? ws[wid - 1] : 0) + base;
    if (i < NN) {
        g_ptr[i] = ex;
        g_pos[i] = ex;
        float d2 = g_dinv2[i] + 1.0f;     // + self loop weight 1
        float di = rsqrtf(d2);
        g_dinv2[i] = di;
        g_nself[i] = di * di;
    }
    if (i == NN - 1) g_ptr[NN] = ex + c;
}

__global__ void k_fill() {
    int e = blockIdx.x * blockDim.x + threadIdx.x;
    if (e >= NE) return;
    int2 rc = g_edge[e];
    float nm = g_dinv2[rc.x] * g_w[e] * g_dinv2[rc.y];
    int p = atomicAdd(&g_pos[rc.y], 1);
    g_csre[p] = make_int2(rc.x, __float_as_int(nm));
}

// HA = x @ W1: persistent grid-stride; thread computes 4 rows x 16 cols,
// f32x2 packed FMA. Grid = 2 blocks/SM exactly -> no wave quantization.
__global__ void __launch_bounds__(256, 2)
k_gemm1(const float* __restrict__ x, const float* __restrict__ W1) {
    __shared__ float Ws[FIN * HID]; // 32 KB
    {
        const float4* w4 = (const float4*)W1;
        float4* s4 = (float4*)Ws;
        for (int i = threadIdx.x; i < FIN * HID / 4; i += blockDim.x) s4[i] = w4[i];
    }
    __syncthreads();
    for (int gt = blockIdx.x * blockDim.x + threadIdx.x; gt < NG * 4;
         gt += gridDim.x * blockDim.x) {
        int grp   = gt >> 2;          // row group (4 rows)
        int slice = gt & 3;           // 16-col slice
        int r0 = grp * 4;
        const float4* xr0 = (const float4*)(x + (long)(r0 + 0) * FIN);
        const float4* xr1 = (const float4*)(x + (long)(r0 + 1) * FIN);
        const float4* xr2 = (const float4*)(x + (long)(r0 + 2) * FIN);
        const float4* xr3 = (const float4*)(x + (long)(r0 + 3) * FIN);
        unsigned long long acc[4][8];   // 4 rows x 8 f32x2 pairs (16 cols)
        #pragma unroll
        for (int i = 0; i < 4; i++)
            #pragma unroll
            for (int j = 0; j < 8; j++) acc[i][j] = 0ull;
        const int cb = slice * 16;
        #pragma unroll 2
        for (int k4 = 0; k4 < FIN / 4; k4++) {
            float4 xv[4] = { xr0[k4], xr1[k4], xr2[k4], xr3[k4] };
            #pragma unroll
            for (int kk = 0; kk < 4; kk++) {
                const ulonglong2* wr = (const ulonglong2*)&Ws[(k4 * 4 + kk) * HID + cb];
                ulonglong2 p0 = wr[0], p1 = wr[1], p2 = wr[2], p3 = wr[3];
                unsigned long long w[8] = { p0.x, p0.y, p1.x, p1.y, p2.x, p2.y, p3.x, p3.y };
                #pragma unroll
                for (int i = 0; i < 4; i++) {
                    float xs = (kk == 0) ? xv[i].x : (kk == 1) ? xv[i].y
                             : (kk == 2) ? xv[i].z : xv[i].w;
                    unsigned long long xs2 = pack2(xs, xs);
                    #pragma unroll
                    for (int j = 0; j < 8; j++) ffma2(acc[i][j], xs2, w[j]);
                }
            }
        }
        #pragma unroll
        for (int i = 0; i < 4; i++) {
            ulonglong2* dst = (ulonglong2*)(g_HA + (long)(r0 + i) * HID + cb);
            #pragma unroll
            for (int j = 0; j < 4; j++)
                dst[j] = make_ulonglong2(acc[i][2 * j], acc[i][2 * j + 1]);
        }
    }
}

// gather-SpMM: warp per destination node, self-loop folded in, x4 unrolled
__global__ void k_spmm_csr() {
    int i = (blockIdx.x * blockDim.x + threadIdx.x) >> 5;
    if (i >= NN) return;
    int lane = threadIdx.x & 31;
    int beg = g_ptr[i], end = g_ptr[i + 1];
    float  ns = g_nself[i];
    float2 h  = ((const float2*)(g_HA + (long)i * HID))[lane];
    float a0 = ns * h.x, a1 = ns * h.y;
    int e = beg;
    for (; e + 4 <= end; e += 4) {
        int2 r0 = g_csre[e + 0];
        int2 r1 = g_csre[e + 1];
        int2 r2 = g_csre[e + 2];
        int2 r3 = g_csre[e + 3];
        float2 v0 = ((const float2*)(g_HA + (long)r0.x * HID))[lane];
        float2 v1 = ((const float2*)(g_HA + (long)r1.x * HID))[lane];
        float2 v2 = ((const float2*)(g_HA + (long)r2.x * HID))[lane];
        float2 v3 = ((const float2*)(g_HA + (long)r3.x * HID))[lane];
        float n0 = __int_as_float(r0.y), n1 = __int_as_float(r1.y);
        float n2 = __int_as_float(r2.y), n3 = __int_as_float(r3.y);
        a0 += n0 * v0.x; a1 += n0 * v0.y;
        a0 += n1 * v1.x; a1 += n1 * v1.y;
        a0 += n2 * v2.x; a1 += n2 * v2.y;
        a0 += n3 * v3.x; a1 += n3 * v3.y;
    }
    for (; e < end; e++) {
        int2  rec = g_csre[e];
        float nm  = __int_as_float(rec.y);
        float2 v  = ((const float2*)(g_HA + (long)rec.x * HID))[lane];
        a0 += nm * v.x;
        a1 += nm * v.y;
    }
    ((float2*)(g_AG + (long)i * HID))[lane] = make_float2(a0, a1);
}

// h1 = relu(AG + b1); HA <- h1 @ W2 : persistent grid-stride, 4x16 tile
__global__ void __launch_bounds__(256, 2)
k_layer1(const float* __restrict__ b1, const float* __restrict__ W2) {
    __shared__ float Ws[HID * HID]; // 16 KB
    __shared__ float bs[HID];
    {
        const float4* w4 = (const float4*)W2;
        float4* s4 = (float4*)Ws;
        for (int i = threadIdx.x; i < HID * HID / 4; i += blockDim.x) s4[i] = w4[i];
        if (threadIdx.x < HID) bs[threadIdx.x] = b1[threadIdx.x];
    }
    __syncthreads();
    for (int gt = blockIdx.x * blockDim.x + threadIdx.x; gt < NG * 4;
         gt += gridDim.x * blockDim.x) {
        int grp   = gt >> 2;
        int slice = gt & 3;
        int r0 = grp * 4;
        const float4* a0p = (const float4*)(g_AG + (long)(r0 + 0) * HID);
        const float4* a1p = (const float4*)(g_AG + (long)(r0 + 1) * HID);
        const float4* a2p = (const float4*)(g_AG + (long)(r0 + 2) * HID);
        const float4* a3p = (const float4*)(g_AG + (long)(r0 + 3) * HID);
        const float4* b4  = (const float4*)bs;
        unsigned long long acc[4][8];
        #pragma unroll
        for (int i = 0; i < 4; i++)
            #pragma unroll
            for (int j = 0; j < 8; j++) acc[i][j] = 0ull;
        const int cb = slice * 16;
        #pragma unroll 2
        for (int k4 = 0; k4 < HID / 4; k4++) {
            float4 bv = b4[k4];
            float4 av[4] = { a0p[k4], a1p[k4], a2p[k4], a3p[k4] };
            float hs[4][4];
            #pragma unroll
            for (int i = 0; i < 4; i++) {
                hs[i][0] = fmaxf(av[i].x + bv.x, 0.f);
                hs[i][1] = fmaxf(av[i].y + bv.y, 0.f);
                hs[i][2] = fmaxf(av[i].z + bv.z, 0.f);
                hs[i][3] = fmaxf(av[i].w + bv.w, 0.f);
            }
            #pragma unroll
            for (int kk = 0; kk < 4; kk++) {
                const ulonglong2* wr = (const ulonglong2*)&Ws[(k4 * 4 + kk) * HID + cb];
                ulonglong2 p0 = wr[0], p1 = wr[1], p2 = wr[2], p3 = wr[3];
                unsigned long long w[8] = { p0.x, p0.y, p1.x, p1.y, p2.x, p2.y, p3.x, p3.y };
                #pragma unroll
                for (int i = 0; i < 4; i++) {
                    unsigned long long xs2 = pack2(hs[i][kk], hs[i][kk]);
                    #pragma unroll
                    for (int j = 0; j < 8; j++) ffma2(acc[i][j], xs2, w[j]);
                }
            }
        }
        #pragma unroll
        for (int i = 0; i < 4; i++) {
            ulonglong2* dst = (ulonglong2*)(g_HA + (long)(r0 + i) * HID + cb);
            #pragma unroll
            for (int j = 0; j < 4; j++)
                dst[j] = make_ulonglong2(acc[i][2 * j], acc[i][2 * j + 1]);
        }
    }
}

// h2 = relu(AG + b2); out = h2 @ Wout + bout : thread per row
__global__ void k_out(const float* __restrict__ b2, const float* __restrict__ Wout,
                      const float* __restrict__ bout, float* __restrict__ out) {
    __shared__ float Ws[HID * TOUT];
    __shared__ float bs[HID];
    __shared__ float bo[TOUT];
    for (int i = threadIdx.x; i < HID * TOUT; i += blockDim.x) Ws[i] = Wout[i];
    if (threadIdx.x < HID)  bs[threadIdx.x] = b2[threadIdx.x];
    if (threadIdx.x < TOUT) bo[threadIdx.x] = bout[threadIdx.x];
    __syncthreads();
    int row = blockIdx.x * blockDim.x + threadIdx.x;
    if (row >= NN) return;
    const float4* ar = (const float4*)(g_AG + (long)row * HID);
    const float4* b4 = (const float4*)bs;
    float acc[TOUT];
    #pragma unroll
    for (int j = 0; j < TOUT; j++) acc[j] = bo[j];
    #pragma unroll 2
    for (int k4 = 0; k4 < HID / 4; k4++) {
        float4 av = ar[k4];
        float4 bv = b4[k4];
        float hs[4] = { fmaxf(av.x + bv.x, 0.f), fmaxf(av.y + bv.y, 0.f),
                        fmaxf(av.z + bv.z, 0.f), fmaxf(av.w + bv.w, 0.f) };
        #pragma unroll
        for (int kk = 0; kk < 4; kk++) {
            float xs = hs[kk];
            const float* wr = &Ws[(k4 * 4 + kk) * TOUT];
            #pragma unroll
            for (int j = 0; j < TOUT; j++) acc[j] += xs * wr[j];
        }
    }
    float* o = out + (long)row * TOUT;
    #pragma unroll
    for (int j = 0; j < TOUT; j++) o[j] = acc[j];
}

// ---------------- launch ----------------
extern "C" void kernel_launch(void* const* d_in, const int* in_sizes, int n_in,
                              void* d_out, int out_size) {
    const float* x    = (const float*)d_in[0];
    const int*   ei   = (const int*)d_in[1];
    const float* et   = (const float*)d_in[2];
    const float* W1   = (const float*)d_in[3];
    const float* b1   = (const float*)d_in[4];
    const float* W2   = (const float*)d_in[5];
    const float* b2   = (const float*)d_in[6];
    const float* Wout = (const float*)d_in[7];
    const float* bout = (const float*)d_in[8];
    float*       out  = (float*)d_out;

    const int TB = 256;
    const int GEMMB = 2 * NSM;          // exactly one full resident wave

    cudaStream_t s2;
    cudaEvent_t  eFork, eJoin;
    cudaStreamCreateWithFlags(&s2, cudaStreamNonBlocking);
    cudaEventCreateWithFlags(&eFork, cudaEventDisableTiming);
    cudaEventCreateWithFlags(&eJoin, cudaEventDisableTiming);

    // fork: gemm1 runs concurrently with the edge-preprocessing chain
    cudaEventRecord(eFork, 0);
    cudaStreamWaitEvent(s2, eFork, 0);
    k_gemm1<<<GEMMB, TB, 0, s2>>>(x, W1);
    cudaEventRecord(eJoin, s2);

    // main stream: edge preprocessing -> CSR
    k_detect_zero<<<NB, TB>>>(ei);
    k_decay_deg<<<(NE + TB - 1) / TB, TB>>>(ei, et);
    k_ew_deg2<<<(NE + TB - 1) / TB, TB>>>();
    k_scanA<<<NB, TB>>>();
    k_scanC<<<NB, TB>>>();
    k_fill <<<(NE + TB - 1) / TB, TB>>>();

    // join: spmm needs both HA (gemm1) and CSR (fill)
    cudaStreamWaitEvent(0, eJoin, 0);

    k_spmm_csr<<<(NN * 32 + TB - 1) / TB, TB>>>();
    k_layer1<<<GEMMB, TB>>>(b1, W2);
    k_spmm_csr<<<(NN * 32 + TB - 1) / TB, TB>>>();
    k_out<<<NB, TB>>>(b2, Wout, bout, out);
}